// round 2
// baseline (speedup 1.0000x reference)
#include <cuda_runtime.h>
#include <cstdint>

#define T_STEPS 1024
#define BATCH   64
#define DIN     256
#define HID     512
#define OUTD    256
#define G3      1536   // 3*HID

// ---------------- persistent scratch (device globals; no allocation) ----------
__device__ float g_xg[(size_t)T_STEPS * BATCH * G3];   // ~402 MB
__device__ float g_hs[(size_t)T_STEPS * BATCH * HID];  // ~134 MB
__device__ float g_h[2][BATCH * HID];
__device__ unsigned int g_bar;

// ---------------- f32x2 packed-FMA helpers (full-rate FMA on sm_103a) ---------
__device__ __forceinline__ uint64_t pack2(float lo, float hi) {
    uint64_t r;
    asm("mov.b64 %0, {%1, %2};" : "=l"(r) : "f"(lo), "f"(hi));
    return r;
}
__device__ __forceinline__ void fma2(uint64_t& d, uint64_t a, uint64_t b) {
    asm("fma.rn.f32x2 %0, %1, %2, %0;" : "+l"(d) : "l"(a), "l"(b));
}
__device__ __forceinline__ float2 unpack2(uint64_t v) {
    float2 f;
    asm("mov.b64 {%0, %1}, %2;" : "=f"(f.x), "=f"(f.y) : "l"(v));
    return f;
}

// =============================================================================
// Generic SGEMM with bias: C[M,N] = A[M,K] @ B[K,N] + bias[N]
// 128x128 tile, BK=16, 256 threads, 8x8 per thread, f32x2 packed FMA.
// Requires M%128==0, N%128==0, K%16==0 (true for all our shapes).
// =============================================================================
__global__ void __launch_bounds__(256) sgemm_bias(
    const float* __restrict__ A, const float* __restrict__ B,
    const float* __restrict__ bias, float* __restrict__ C,
    int M, int N, int K)
{
    constexpr int BM = 128, BN = 128, BK = 16;
    __shared__ __align__(16) float As[BK][BM];   // A stored k-major (transposed)
    __shared__ __align__(16) float Bs[BK][BN];

    const int tid  = threadIdx.x;
    const int bm   = blockIdx.y * BM;
    const int bn   = blockIdx.x * BN;
    const int trow = (tid >> 4) * 8;    // 0..120
    const int tcol = (tid & 15) * 8;    // 0..120

    uint64_t acc[4][8];
#pragma unroll
    for (int i = 0; i < 4; i++)
#pragma unroll
        for (int j = 0; j < 8; j++) acc[i][j] = 0ull;  // {0.f,0.f}

    for (int k0 = 0; k0 < K; k0 += BK) {
        // ---- load A tile [BM][BK], store transposed into As[BK][BM]
#pragma unroll
        for (int l = 0; l < 2; l++) {
            int c   = tid * 2 + l;          // 0..511
            int row = c >> 2;
            int kq  = (c & 3) * 4;
            float4 v = *(const float4*)(A + (size_t)(bm + row) * K + k0 + kq);
            As[kq + 0][row] = v.x;
            As[kq + 1][row] = v.y;
            As[kq + 2][row] = v.z;
            As[kq + 3][row] = v.w;
        }
        // ---- load B tile [BK][BN]
#pragma unroll
        for (int l = 0; l < 2; l++) {
            int c  = tid + (l << 8);        // 0..511
            int kr = c >> 5;
            int n4 = (c & 31) * 4;
            *(float4*)&Bs[kr][n4] =
                *(const float4*)(B + (size_t)(k0 + kr) * N + bn + n4);
        }
        __syncthreads();

#pragma unroll
        for (int kk = 0; kk < BK; kk++) {
            float4 a0 = *(const float4*)&As[kk][trow];
            float4 a1 = *(const float4*)&As[kk][trow + 4];
            float4 b0 = *(const float4*)&Bs[kk][tcol];
            float4 b1 = *(const float4*)&Bs[kk][tcol + 4];
            uint64_t ap[4];
            ap[0] = pack2(a0.x, a0.y);
            ap[1] = pack2(a0.z, a0.w);
            ap[2] = pack2(a1.x, a1.y);
            ap[3] = pack2(a1.z, a1.w);
            float bf[8] = {b0.x, b0.y, b0.z, b0.w, b1.x, b1.y, b1.z, b1.w};
#pragma unroll
            for (int j = 0; j < 8; j++) {
                uint64_t bd = pack2(bf[j], bf[j]);
#pragma unroll
                for (int i = 0; i < 4; i++) fma2(acc[i][j], ap[i], bd);
            }
        }
        __syncthreads();
    }

    // ---- epilogue: add bias, write 8x8 block
    float bv[8];
#pragma unroll
    for (int j = 0; j < 8; j++) bv[j] = bias[bn + tcol + j];

#pragma unroll
    for (int i = 0; i < 4; i++) {
        float o0[8], o1[8];
#pragma unroll
        for (int j = 0; j < 8; j++) {
            float2 v = unpack2(acc[i][j]);
            o0[j] = v.x + bv[j];
            o1[j] = v.y + bv[j];
        }
        size_t r0 = (size_t)(bm + trow + 2 * i) * N + bn + tcol;
        size_t r1 = r0 + N;
        *(float4*)(C + r0)     = make_float4(o0[0], o0[1], o0[2], o0[3]);
        *(float4*)(C + r0 + 4) = make_float4(o0[4], o0[5], o0[6], o0[7]);
        *(float4*)(C + r1)     = make_float4(o1[0], o1[1], o1[2], o1[3]);
        *(float4*)(C + r1 + 4) = make_float4(o1[4], o1[5], o1[6], o1[7]);
    }
}

// =============================================================================
// Persistent GRU scan.
// Grid: 128 CTAs x 256 threads. CTA owns 4 hidden columns (j0..j0+3), holds
// the 12 corresponding Wh columns in SMEM. Thread = (batch b = tid/4, jl = tid%4).
// Per step: 3 dot products of length 512 (f32x2), gating, grid barrier.
// h double-buffered in g_h; reads via __ldcg (L2-coherent across CTAs).
// =============================================================================
__global__ void __launch_bounds__(256) gru_scan(
    const float* __restrict__ Wh, const float* __restrict__ bhn)
{
    __shared__ __align__(16) float wsm[3][4][520];  // 520 pad: conflict-free LDS.128

    const int tid = threadIdx.x;
    const int j0  = blockIdx.x * 4;

    // one-time Wh column load (strided, amortized over 1024 steps)
    for (int i = tid; i < 3 * 4 * 512; i += 256) {
        int g  = i >> 11;         // 0..2
        int jl = (i >> 9) & 3;    // 0..3
        int k  = i & 511;         // 0..511
        wsm[g][jl][k] = Wh[(size_t)k * G3 + g * HID + j0 + jl];
    }
    __syncthreads();

    const int b  = tid >> 2;
    const int jl = tid & 3;
    const int j  = j0 + jl;
    const float bh = bhn[j];

    const ulonglong2* wr = (const ulonglong2*)wsm[0][jl];
    const ulonglong2* wz = (const ulonglong2*)wsm[1][jl];
    const ulonglong2* wn = (const ulonglong2*)wsm[2][jl];

    const unsigned nblk = gridDim.x;

    for (int t = 0; t < T_STEPS; t++) {
        const float* hread  = g_h[t & 1];
        float*       hwrite = g_h[(t & 1) ^ 1];
        const float4* hrow  = (const float4*)(hread + b * HID);

        uint64_t ar = 0ull, az = 0ull, an = 0ull;
#pragma unroll 4
        for (int k4 = 0; k4 < HID / 4; k4++) {
            float4 hv = __ldcg(&hrow[k4]);
            uint64_t h01 = pack2(hv.x, hv.y);
            uint64_t h23 = pack2(hv.z, hv.w);
            ulonglong2 w;
            w = wr[k4]; fma2(ar, h01, w.x); fma2(ar, h23, w.y);
            w = wz[k4]; fma2(az, h01, w.x); fma2(az, h23, w.y);
            w = wn[k4]; fma2(an, h01, w.x); fma2(an, h23, w.y);
        }
        float2 f;
        f = unpack2(ar); float hr = f.x + f.y;
        f = unpack2(az); float hz = f.x + f.y;
        f = unpack2(an); float hn = f.x + f.y;

        size_t xb = ((size_t)t * BATCH + b) * G3 + j;
        float xr = g_xg[xb];
        float xz = g_xg[xb + HID];
        float xn = g_xg[xb + 2 * HID];

        float r = 1.f / (1.f + __expf(-(xr + hr)));
        float z = 1.f / (1.f + __expf(-(xz + hz)));
        float n = tanhf(xn + r * (hn + bh));
        float hp = __ldcg(&hread[b * HID + j]);
        float hnew = (1.f - z) * n + z * hp;

        hwrite[b * HID + j] = hnew;
        g_hs[((size_t)t * BATCH + b) * HID + j] = hnew;

        // ---- grid barrier (release/acquire, monotonic counter) ----
        __syncthreads();
        if (tid == 0) {
            __threadfence();                       // release my CTA's writes
            atomicAdd(&g_bar, 1u);
            unsigned target = nblk * (unsigned)(t + 1);
            while (*((volatile unsigned*)&g_bar) < target) { }
            __threadfence();                       // acquire others' writes
        }
        __syncthreads();
    }
}

// =============================================================================
extern "C" void kernel_launch(void* const* d_in, const int* in_sizes, int n_in,
                              void* d_out, int out_size)
{
    const float* x   = (const float*)d_in[0];
    const float* Wi  = (const float*)d_in[1];
    const float* bi  = (const float*)d_in[2];
    const float* Wh  = (const float*)d_in[3];
    const float* bhn = (const float*)d_in[4];
    const float* Wo  = (const float*)d_in[5];
    const float* bo  = (const float*)d_in[6];
    const float* h0  = (const float*)d_in[7];
    float* out = (float*)d_out;

    void *xg_p, *hs_p, *h_p, *bar_p;
    cudaGetSymbolAddress(&xg_p, g_xg);
    cudaGetSymbolAddress(&hs_p, g_hs);
    cudaGetSymbolAddress(&h_p,  g_h);
    cudaGetSymbolAddress(&bar_p, g_bar);

    // reset barrier counter + seed h0 (graph-capturable stream ops)
    cudaMemsetAsync(bar_p, 0, sizeof(unsigned), 0);
    cudaMemcpyAsync(h_p, h0, (size_t)BATCH * HID * sizeof(float),
                    cudaMemcpyDeviceToDevice, 0);

    // 1) xg = x @ Wi + bi   : [65536,256]x[256,1536]
    {
        dim3 grid(G3 / 128, (T_STEPS * BATCH) / 128);
        sgemm_bias<<<grid, 256>>>(x, Wi, bi, (float*)xg_p,
                                  T_STEPS * BATCH, G3, DIN);
    }

    // 2) persistent GRU scan over T=1024 steps
    gru_scan<<<HID / 4, 256>>>(Wh, bhn);

    // 3) out = hs @ Wo + bo : [65536,512]x[512,256]
    {
        dim3 grid(OUTD / 128, (T_STEPS * BATCH) / 128);
        sgemm_bias<<<grid, 256>>>((const float*)hs_p, Wo, bo, out,
                                  T_STEPS * BATCH, OUTD, HID);
    }
}

// round 3
// speedup vs baseline: 1.6842x; 1.6842x over previous
#include <cuda_runtime.h>
#include <cstdint>

#define T_STEPS 1024
#define BATCH   64
#define DIN     256
#define HID     512
#define OUTD    256
#define G3      1536   // 3*HID

// ---------------- persistent scratch (device globals; no allocation) ----------
__device__ float g_xg[(size_t)T_STEPS * BATCH * G3];   // ~402 MB
__device__ float g_hs[(size_t)T_STEPS * BATCH * HID];  // ~134 MB
__device__ float g_h[2][BATCH * HID];
__device__ unsigned int g_bar;

// ---------------- f32x2 packed-FMA helpers (full-rate FMA on sm_103a) ---------
__device__ __forceinline__ void fma2(uint64_t& d, uint64_t a, uint64_t b) {
    asm("fma.rn.f32x2 %0, %1, %2, %0;" : "+l"(d) : "l"(a), "l"(b));
}
__device__ __forceinline__ uint64_t pack2(float lo, float hi) {
    uint64_t r;
    asm("mov.b64 %0, {%1, %2};" : "=l"(r) : "f"(lo), "f"(hi));
    return r;
}
__device__ __forceinline__ float2 unpack2(uint64_t v) {
    float2 f;
    asm("mov.b64 {%0, %1}, %2;" : "=f"(f.x), "=f"(f.y) : "l"(v));
    return f;
}
__device__ __forceinline__ void cp_async16(void* smem_dst, const void* gmem_src) {
    uint32_t s;
    asm("{ .reg .u64 t; cvta.to.shared.u64 t, %1; cvt.u32.u64 %0, t; }"
        : "=r"(s) : "l"(smem_dst));
    asm volatile("cp.async.cg.shared.global [%0], [%1], 16;" :: "r"(s), "l"(gmem_src));
}

// =============================================================================
// Generic SGEMM with bias: C[M,N] = A[M,K] @ B[K,N] + bias[N]
// 128x128 tile, BK=16, 256 threads, 8x8 per thread, f32x2 packed FMA.
// =============================================================================
__global__ void __launch_bounds__(256) sgemm_bias(
    const float* __restrict__ A, const float* __restrict__ B,
    const float* __restrict__ bias, float* __restrict__ C,
    int M, int N, int K)
{
    constexpr int BM = 128, BN = 128, BK = 16;
    __shared__ __align__(16) float As[BK][BM];
    __shared__ __align__(16) float Bs[BK][BN];

    const int tid  = threadIdx.x;
    const int bm   = blockIdx.y * BM;
    const int bn   = blockIdx.x * BN;
    const int trow = (tid >> 4) * 8;
    const int tcol = (tid & 15) * 8;

    uint64_t acc[4][8];
#pragma unroll
    for (int i = 0; i < 4; i++)
#pragma unroll
        for (int j = 0; j < 8; j++) acc[i][j] = 0ull;

    for (int k0 = 0; k0 < K; k0 += BK) {
#pragma unroll
        for (int l = 0; l < 2; l++) {
            int c   = tid * 2 + l;
            int row = c >> 2;
            int kq  = (c & 3) * 4;
            float4 v = *(const float4*)(A + (size_t)(bm + row) * K + k0 + kq);
            As[kq + 0][row] = v.x;
            As[kq + 1][row] = v.y;
            As[kq + 2][row] = v.z;
            As[kq + 3][row] = v.w;
        }
#pragma unroll
        for (int l = 0; l < 2; l++) {
            int c  = tid + (l << 8);
            int kr = c >> 5;
            int n4 = (c & 31) * 4;
            *(float4*)&Bs[kr][n4] =
                *(const float4*)(B + (size_t)(k0 + kr) * N + bn + n4);
        }
        __syncthreads();

#pragma unroll
        for (int kk = 0; kk < BK; kk++) {
            float4 a0 = *(const float4*)&As[kk][trow];
            float4 a1 = *(const float4*)&As[kk][trow + 4];
            float4 b0 = *(const float4*)&Bs[kk][tcol];
            float4 b1 = *(const float4*)&Bs[kk][tcol + 4];
            uint64_t ap[4];
            ap[0] = pack2(a0.x, a0.y);
            ap[1] = pack2(a0.z, a0.w);
            ap[2] = pack2(a1.x, a1.y);
            ap[3] = pack2(a1.z, a1.w);
            float bf[8] = {b0.x, b0.y, b0.z, b0.w, b1.x, b1.y, b1.z, b1.w};
#pragma unroll
            for (int j = 0; j < 8; j++) {
                uint64_t bd = pack2(bf[j], bf[j]);
#pragma unroll
                for (int i = 0; i < 4; i++) fma2(acc[i][j], ap[i], bd);
            }
        }
        __syncthreads();
    }

    float bv[8];
#pragma unroll
    for (int j = 0; j < 8; j++) bv[j] = bias[bn + tcol + j];

#pragma unroll
    for (int i = 0; i < 4; i++) {
        float o0[8], o1[8];
#pragma unroll
        for (int j = 0; j < 8; j++) {
            float2 v = unpack2(acc[i][j]);
            o0[j] = v.x + bv[j];
            o1[j] = v.y + bv[j];
        }
        size_t r0 = (size_t)(bm + trow + 2 * i) * N + bn + tcol;
        size_t r1 = r0 + N;
        *(float4*)(C + r0)     = make_float4(o0[0], o0[1], o0[2], o0[3]);
        *(float4*)(C + r0 + 4) = make_float4(o0[4], o0[5], o0[6], o0[7]);
        *(float4*)(C + r1)     = make_float4(o1[0], o1[1], o1[2], o1[3]);
        *(float4*)(C + r1 + 4) = make_float4(o1[4], o1[5], o1[6], o1[7]);
    }
}

// =============================================================================
// Persistent GRU scan v2.
// 128 CTAs x 256 threads, 1 CTA/SM (157KB dyn SMEM). CTA owns 4 hidden cols;
// Wh cols resident in SMEM for all 1024 steps. Each step:
//   - prefetch xg (DRAM) into regs
//   - bulk-copy h (128KB) global->SMEM via cp.async in 4 pipelined k-chunks
//   - dot products from SMEM (ld.shared.v2.u64 + fma.rn.f32x2)
//   - gating, store h_new (double-buffered global) + hs
//   - grid barrier
// =============================================================================
#define HPAD 516          // h_sm row stride (floats): b-offset = 4 banks -> conflict-free
#define WPAD 520          // w row stride: jl-offset = 8 banks -> conflict-free

__global__ void __launch_bounds__(256) gru_scan(
    const float* __restrict__ Wh, const float* __restrict__ bhn)
{
    extern __shared__ float smem[];
    float* h_sm = smem;                       // [64][HPAD]
    float* wsm  = smem + BATCH * HPAD;        // [3][4][WPAD]

    const int tid = threadIdx.x;
    const int j0  = blockIdx.x * 4;

    // one-time Wh column load (amortized over 1024 steps)
    for (int i = tid; i < 3 * 4 * HID; i += 256) {
        int g  = i >> 11;
        int jl = (i >> 9) & 3;
        int k  = i & 511;
        wsm[(g * 4 + jl) * WPAD + k] = Wh[(size_t)k * G3 + g * HID + j0 + jl];
    }
    __syncthreads();

    const int b  = tid >> 2;
    const int jl = tid & 3;
    const int j  = j0 + jl;
    const float bh = bhn[j];

    const ulonglong2* wr = (const ulonglong2*)(wsm + (0 * 4 + jl) * WPAD);
    const ulonglong2* wz = (const ulonglong2*)(wsm + (1 * 4 + jl) * WPAD);
    const ulonglong2* wn = (const ulonglong2*)(wsm + (2 * 4 + jl) * WPAD);
    const ulonglong2* hme = (const ulonglong2*)(h_sm + b * HPAD);

    const unsigned nblk = gridDim.x;

    for (int t = 0; t < T_STEPS; t++) {
        const float* hread  = g_h[t & 1];
        float*       hwrite = g_h[(t & 1) ^ 1];

        // ---- prefetch xg (DRAM latency hides under the h copy) ----
        size_t xb = ((size_t)t * BATCH + b) * G3 + j;
        float xr = __ldcg(&g_xg[xb]);
        float xz = __ldcg(&g_xg[xb + HID]);
        float xn = __ldcg(&g_xg[xb + 2 * HID]);

        // ---- issue h copy: 4 chunks of 32 k4 (32KB each), 8 LDGSTS/thread ----
#pragma unroll
        for (int c = 0; c < 4; c++) {
#pragma unroll
            for (int i = 0; i < 8; i++) {
                int idx  = tid + i * 256;          // 0..2047 within chunk
                int row  = idx >> 5;               // 0..63
                int k4l  = idx & 31;
                int kf   = (c * 32 + k4l) * 4;     // float offset within row
                cp_async16(h_sm + row * HPAD + kf,
                           hread + row * HID + kf);
            }
            asm volatile("cp.async.commit_group;");
        }

        // ---- dot products, chunk-pipelined ----
        uint64_t ar = 0ull, az = 0ull, an = 0ull;
#pragma unroll
        for (int c = 0; c < 4; c++) {
            if      (c == 0) asm volatile("cp.async.wait_group 3;");
            else if (c == 1) asm volatile("cp.async.wait_group 2;");
            else if (c == 2) asm volatile("cp.async.wait_group 1;");
            else             asm volatile("cp.async.wait_group 0;");
            __syncthreads();

#pragma unroll 8
            for (int k4 = c * 32; k4 < c * 32 + 32; k4++) {
                ulonglong2 hv = hme[k4];
                ulonglong2 w;
                w = wr[k4]; fma2(ar, hv.x, w.x); fma2(ar, hv.y, w.y);
                w = wz[k4]; fma2(az, hv.x, w.x); fma2(az, hv.y, w.y);
                w = wn[k4]; fma2(an, hv.x, w.x); fma2(an, hv.y, w.y);
            }
        }
        float2 f;
        f = unpack2(ar); float hr = f.x + f.y;
        f = unpack2(az); float hz = f.x + f.y;
        f = unpack2(an); float hn = f.x + f.y;

        float r = 1.f / (1.f + __expf(-(xr + hr)));
        float z = 1.f / (1.f + __expf(-(xz + hz)));
        float n = tanhf(xn + r * (hn + bh));
        float hp = h_sm[b * HPAD + j];
        float hnew = (1.f - z) * n + z * hp;

        hwrite[b * HID + j] = hnew;
        g_hs[((size_t)t * BATCH + b) * HID + j] = hnew;

        // ---- grid barrier (release/acquire, monotonic counter) ----
        __syncthreads();
        if (tid == 0) {
            __threadfence();
            atomicAdd(&g_bar, 1u);
            unsigned target = nblk * (unsigned)(t + 1);
            while (*((volatile unsigned*)&g_bar) < target) { }
            __threadfence();
        }
        __syncthreads();
    }
}

// =============================================================================
extern "C" void kernel_launch(void* const* d_in, const int* in_sizes, int n_in,
                              void* d_out, int out_size)
{
    const float* x   = (const float*)d_in[0];
    const float* Wi  = (const float*)d_in[1];
    const float* bi  = (const float*)d_in[2];
    const float* Wh  = (const float*)d_in[3];
    const float* bhn = (const float*)d_in[4];
    const float* Wo  = (const float*)d_in[5];
    const float* bo  = (const float*)d_in[6];
    const float* h0  = (const float*)d_in[7];
    float* out = (float*)d_out;

    void *xg_p, *hs_p, *h_p, *bar_p;
    cudaGetSymbolAddress(&xg_p, g_xg);
    cudaGetSymbolAddress(&hs_p, g_hs);
    cudaGetSymbolAddress(&h_p,  g_h);
    cudaGetSymbolAddress(&bar_p, g_bar);

    // scan kernel needs 157KB dynamic SMEM (idempotent; host-side, not captured)
    static_assert((BATCH * HPAD + 3 * 4 * WPAD) * sizeof(float) == 157056, "smem");
    cudaFuncSetAttribute(gru_scan, cudaFuncAttributeMaxDynamicSharedMemorySize,
                         (BATCH * HPAD + 3 * 4 * WPAD) * sizeof(float));

    cudaMemsetAsync(bar_p, 0, sizeof(unsigned), 0);
    cudaMemcpyAsync(h_p, h0, (size_t)BATCH * HID * sizeof(float),
                    cudaMemcpyDeviceToDevice, 0);

    // 1) xg = x @ Wi + bi   : [65536,256]x[256,1536]
    {
        dim3 grid(G3 / 128, (T_STEPS * BATCH) / 128);
        sgemm_bias<<<grid, 256>>>(x, Wi, bi, (float*)xg_p,
                                  T_STEPS * BATCH, G3, DIN);
    }

    // 2) persistent GRU scan over T=1024 steps
    gru_scan<<<HID / 4, 256,
               (BATCH * HPAD + 3 * 4 * WPAD) * sizeof(float)>>>(Wh, bhn);

    // 3) out = hs @ Wo + bo : [65536,512]x[512,256]
    {
        dim3 grid(OUTD / 128, (T_STEPS * BATCH) / 128);
        sgemm_bias<<<grid, 256>>>((const float*)hs_p, Wo, bo, out,
                                  T_STEPS * BATCH, OUTD, HID);
    }
}

// round 7
// speedup vs baseline: 1.8156x; 1.0780x over previous
#include <cuda_runtime.h>
#include <cstdint>

#define T_STEPS 1024
#define BATCH   64
#define DIN     256
#define HID     512
#define OUTD    256
#define G3      1536   // 3*HID

// ---------------- persistent scratch (device globals; no allocation) ----------
__device__ float g_xg[(size_t)T_STEPS * BATCH * G3];   // ~402 MB
__device__ float g_hs[(size_t)T_STEPS * BATCH * HID];  // ~134 MB
__device__ float g_h[2][BATCH * HID];
__device__ unsigned int g_bar;

// ---------------- packed f32x2 helpers ---------------------------------------
__device__ __forceinline__ void fma2(uint64_t& d, uint64_t a, uint64_t b) {
    asm("fma.rn.f32x2 %0, %1, %2, %0;" : "+l"(d) : "l"(a), "l"(b));
}
__device__ __forceinline__ uint64_t pack2(float lo, float hi) {
    uint64_t r;
    asm("mov.b64 %0, {%1, %2};" : "=l"(r) : "f"(lo), "f"(hi));
    return r;
}
__device__ __forceinline__ float2 unpack2(uint64_t v) {
    float2 f;
    asm("mov.b64 {%0, %1}, %2;" : "=f"(f.x), "=f"(f.y) : "l"(v));
    return f;
}
// 16B L2-coherent global load into two 64-bit (f32x2) registers
__device__ __forceinline__ void ldcg_v2u64(uint64_t& a, uint64_t& b, const void* p) {
    asm volatile("ld.global.cg.v2.u64 {%0, %1}, [%2];" : "=l"(a), "=l"(b) : "l"(p));
}

// =============================================================================
// Generic SGEMM with bias: C[M,N] = A[M,K] @ B[K,N] + bias[N]
// 128x128 tile, BK=16, 256 threads, 8x8 per thread, f32x2 packed FMA.
// =============================================================================
__global__ void __launch_bounds__(256) sgemm_bias(
    const float* __restrict__ A, const float* __restrict__ B,
    const float* __restrict__ bias, float* __restrict__ C,
    int M, int N, int K)
{
    constexpr int BM = 128, BN = 128, BK = 16;
    __shared__ __align__(16) float As[BK][BM];
    __shared__ __align__(16) float Bs[BK][BN];

    const int tid  = threadIdx.x;
    const int bm   = blockIdx.y * BM;
    const int bn   = blockIdx.x * BN;
    const int trow = (tid >> 4) * 8;
    const int tcol = (tid & 15) * 8;

    uint64_t acc[4][8];
#pragma unroll
    for (int i = 0; i < 4; i++)
#pragma unroll
        for (int j = 0; j < 8; j++) acc[i][j] = 0ull;

    for (int k0 = 0; k0 < K; k0 += BK) {
#pragma unroll
        for (int l = 0; l < 2; l++) {
            int c   = tid * 2 + l;
            int row = c >> 2;
            int kq  = (c & 3) * 4;
            float4 v = *(const float4*)(A + (size_t)(bm + row) * K + k0 + kq);
            As[kq + 0][row] = v.x;
            As[kq + 1][row] = v.y;
            As[kq + 2][row] = v.z;
            As[kq + 3][row] = v.w;
        }
#pragma unroll
        for (int l = 0; l < 2; l++) {
            int c  = tid + (l << 8);
            int kr = c >> 5;
            int n4 = (c & 31) * 4;
            *(float4*)&Bs[kr][n4] =
                *(const float4*)(B + (size_t)(k0 + kr) * N + bn + n4);
        }
        __syncthreads();

#pragma unroll
        for (int kk = 0; kk < BK; kk++) {
            float4 a0 = *(const float4*)&As[kk][trow];
            float4 a1 = *(const float4*)&As[kk][trow + 4];
            float4 b0 = *(const float4*)&Bs[kk][tcol];
            float4 b1 = *(const float4*)&Bs[kk][tcol + 4];
            uint64_t ap[4];
            ap[0] = pack2(a0.x, a0.y);
            ap[1] = pack2(a0.z, a0.w);
            ap[2] = pack2(a1.x, a1.y);
            ap[3] = pack2(a1.z, a1.w);
            float bf[8] = {b0.x, b0.y, b0.z, b0.w, b1.x, b1.y, b1.z, b1.w};
#pragma unroll
            for (int j = 0; j < 8; j++) {
                uint64_t bd = pack2(bf[j], bf[j]);
#pragma unroll
                for (int i = 0; i < 4; i++) fma2(acc[i][j], ap[i], bd);
            }
        }
        __syncthreads();
    }

    float bv[8];
#pragma unroll
    for (int j = 0; j < 8; j++) bv[j] = bias[bn + tcol + j];

#pragma unroll
    for (int i = 0; i < 4; i++) {
        float o0[8], o1[8];
#pragma unroll
        for (int j = 0; j < 8; j++) {
            float2 v = unpack2(acc[i][j]);
            o0[j] = v.x + bv[j];
            o1[j] = v.y + bv[j];
        }
        size_t r0 = (size_t)(bm + trow + 2 * i) * N + bn + tcol;
        size_t r1 = r0 + N;
        *(float4*)(C + r0)     = make_float4(o0[0], o0[1], o0[2], o0[3]);
        *(float4*)(C + r0 + 4) = make_float4(o0[4], o0[5], o0[6], o0[7]);
        *(float4*)(C + r1)     = make_float4(o1[0], o1[1], o1[2], o1[3]);
        *(float4*)(C + r1 + 4) = make_float4(o1[4], o1[5], o1[6], o1[7]);
    }
}

// =============================================================================
// Persistent GRU scan v3 — broadcast-W / register-h layout.
//
// 128 CTAs x 512 threads, 1 CTA/SM. CTA owns 4 hidden cols j0..j0+3 (12 gate
// columns). W stored in SMEM k-pair-interleaved: wsm2[kp][c] = (W[2kp,c],
// W[2kp+1,c]) so reads are warp-uniform broadcast LDS.128 (1 phase each).
// Thread = (b = tid&63, kq = tid>>6): loads its private h[b, kq*64..+63]
// slice from global (L2) into registers, accumulates 12 f32x2 partials,
// reduces across the 8 k-segments via padded SMEM, gates, stores.
// =============================================================================
#define NT   512
#define RPAD 97            // red row stride (floats), odd -> conflict-free
#define SCAN_SMEM (2 * 256 * 12 * 4 + BATCH * RPAD * 4)   // 49408 B

__global__ void __launch_bounds__(NT, 1) gru_scan(
    const float* __restrict__ Wh, const float* __restrict__ bhn)
{
    extern __shared__ float smem[];
    float2* wsm2 = (float2*)smem;              // [256 kp][12 c]
    float*  red  = smem + 2 * 256 * 12;        // [64][RPAD]

    const int tid = threadIdx.x;
    const int j0  = blockIdx.x * 4;

    // one-time W load, k-pair interleaved; c = jl*3 + g
    for (int i = tid; i < 256 * 12; i += NT) {
        int kp = i / 12, c = i % 12;
        int jl = c / 3, g = c - jl * 3;
        int col = g * HID + j0 + jl;
        float2 v;
        v.x = Wh[(size_t)(2 * kp)     * G3 + col];
        v.y = Wh[(size_t)(2 * kp + 1) * G3 + col];
        wsm2[i] = v;
    }
    __syncthreads();

    const int b   = tid & 63;        // compute role: batch
    const int kq  = tid >> 6;        // compute role: k-segment (0..7)
    const int rb  = tid >> 2;        // reducer role: batch   (tid < 256)
    const int rjl = tid & 3;         // reducer role: local j
    const float bh = bhn[j0 + rjl];

    // warp-uniform W pointer for this k-segment (all lanes share kq)
    const ulonglong2* wp =
        (const ulonglong2*)(wsm2 + (size_t)kq * 32 * 12);

    const unsigned nblk = gridDim.x;

    for (int t = 0; t < T_STEPS; t++) {
        const float* hread  = g_h[t & 1];
        float*       hwrite = g_h[(t & 1) ^ 1];

        // ---- reducer-role prefetches (DRAM xg + prev-h), hide under compute
        float xr = 0.f, xz = 0.f, xn = 0.f, hp = 0.f;
        if (tid < 256) {
            size_t xb = ((size_t)t * BATCH + rb) * G3 + j0 + rjl;
            xr = __ldcg(&g_xg[xb]);
            xz = __ldcg(&g_xg[xb + HID]);
            xn = __ldcg(&g_xg[xb + 2 * HID]);
            hp = __ldcg(&hread[rb * HID + j0 + rjl]);
        }

        // ---- load private h slice (64 floats) from L2 into registers
        uint64_t h2[32];
        {
            const char* hbase =
                (const char*)(hread + (size_t)b * HID + kq * 64);
#pragma unroll
            for (int i = 0; i < 16; i++)
                ldcg_v2u64(h2[2 * i], h2[2 * i + 1], hbase + i * 16);
        }

        // ---- 12 broadcast dot products over 32 k-pairs
        uint64_t acc[12];
#pragma unroll
        for (int c = 0; c < 12; c++) acc[c] = 0ull;

#pragma unroll
        for (int l = 0; l < 32; l++) {
            uint64_t hv = h2[l];
#pragma unroll
            for (int m = 0; m < 6; m++) {
                ulonglong2 w = wp[l * 6 + m];     // broadcast: 1 phase
                fma2(acc[2 * m],     hv, w.x);
                fma2(acc[2 * m + 1], hv, w.y);
            }
        }

        // ---- write partials (horizontal-add the even/odd-k lanes)
#pragma unroll
        for (int c = 0; c < 12; c++) {
            float2 v = unpack2(acc[c]);
            red[b * RPAD + kq * 12 + c] = v.x + v.y;
        }
        __syncthreads();

        // ---- reduce 8 k-segments, gate, store
        if (tid < 256) {
            float hr = 0.f, hz = 0.f, hn = 0.f;
#pragma unroll
            for (int q = 0; q < 8; q++) {
                const float* rp = red + rb * RPAD + q * 12 + rjl * 3;
                hr += rp[0];
                hz += rp[1];
                hn += rp[2];
            }
            float r = 1.f / (1.f + __expf(-(xr + hr)));
            float z = 1.f / (1.f + __expf(-(xz + hz)));
            float n = tanhf(xn + r * (hn + bh));
            float hnew = (1.f - z) * n + z * hp;

            hwrite[rb * HID + j0 + rjl] = hnew;
            g_hs[((size_t)t * BATCH + rb) * HID + j0 + rjl] = hnew;
        }

        // ---- grid barrier (release/acquire, monotonic counter)
        __syncthreads();
        if (tid == 0) {
            __threadfence();
            atomicAdd(&g_bar, 1u);
            unsigned target = nblk * (unsigned)(t + 1);
            while (*((volatile unsigned*)&g_bar) < target) { }
            __threadfence();
        }
        __syncthreads();
    }
}

// =============================================================================
extern "C" void kernel_launch(void* const* d_in, const int* in_sizes, int n_in,
                              void* d_out, int out_size)
{
    const float* x   = (const float*)d_in[0];
    const float* Wi  = (const float*)d_in[1];
    const float* bi  = (const float*)d_in[2];
    const float* Wh  = (const float*)d_in[3];
    const float* bhn = (const float*)d_in[4];
    const float* Wo  = (const float*)d_in[5];
    const float* bo  = (const float*)d_in[6];
    const float* h0  = (const float*)d_in[7];
    float* out = (float*)d_out;

    void *xg_p, *hs_p, *h_p, *bar_p;
    cudaGetSymbolAddress(&xg_p, g_xg);
    cudaGetSymbolAddress(&hs_p, g_hs);
    cudaGetSymbolAddress(&h_p,  g_h);
    cudaGetSymbolAddress(&bar_p, g_bar);

    cudaFuncSetAttribute(gru_scan, cudaFuncAttributeMaxDynamicSharedMemorySize,
                         SCAN_SMEM);

    cudaMemsetAsync(bar_p, 0, sizeof(unsigned), 0);
    cudaMemcpyAsync(h_p, h0, (size_t)BATCH * HID * sizeof(float),
                    cudaMemcpyDeviceToDevice, 0);

    // 1) xg = x @ Wi + bi   : [65536,256]x[256,1536]
    {
        dim3 grid(G3 / 128, (T_STEPS * BATCH) / 128);
        sgemm_bias<<<grid, 256>>>(x, Wi, bi, (float*)xg_p,
                                  T_STEPS * BATCH, G3, DIN);
    }

    // 2) persistent GRU scan over T=1024 steps
    gru_scan<<<HID / 4, NT, SCAN_SMEM>>>(Wh, bhn);

    // 3) out = hs @ Wo + bo : [65536,512]x[512,256]
    {
        dim3 grid(OUTD / 128, (T_STEPS * BATCH) / 128);
        sgemm_bias<<<grid, 256>>>((const float*)hs_p, Wo, bo, out,
                                  T_STEPS * BATCH, OUTD, HID);
    }
}

// round 8
// speedup vs baseline: 2.4967x; 1.3751x over previous
#include <cuda_runtime.h>
#include <cstdint>

#define T_STEPS 1024
#define BATCH   64
#define DIN     256
#define HID     512
#define OUTD    256
#define G3      1536   // 3*HID
#define HROW    516    // padded h row stride (floats); sigma=129 odd -> conflict-free

// ---------------- persistent scratch (device globals; no allocation) ----------
__device__ float g_xg[(size_t)T_STEPS * BATCH * G3];   // ~402 MB
__device__ float g_hs[(size_t)T_STEPS * BATCH * HID];  // ~134 MB
__device__ __align__(256) float g_h[2][BATCH * HROW];  // padded, bulk-copyable
__device__ unsigned int g_bar;

// ---------------- packed f32x2 + async helpers --------------------------------
__device__ __forceinline__ void fma2(uint64_t& d, uint64_t a, uint64_t b) {
    asm("fma.rn.f32x2 %0, %1, %2, %0;" : "+l"(d) : "l"(a), "l"(b));
}
__device__ __forceinline__ uint64_t pack2(float lo, float hi) {
    uint64_t r;
    asm("mov.b64 %0, {%1, %2};" : "=l"(r) : "f"(lo), "f"(hi));
    return r;
}
__device__ __forceinline__ float2 unpack2(uint64_t v) {
    float2 f;
    asm("mov.b64 {%0, %1}, %2;" : "=f"(f.x), "=f"(f.y) : "l"(v));
    return f;
}
__device__ __forceinline__ uint32_t smem_u32(const void* p) {
    uint32_t a;
    asm("{ .reg .u64 t; cvta.to.shared.u64 t, %1; cvt.u32.u64 %0, t; }"
        : "=r"(a) : "l"(p));
    return a;
}
__device__ __forceinline__ void mbar_init(uint32_t mbar, uint32_t cnt) {
    asm volatile("mbarrier.init.shared.b64 [%0], %1;" :: "r"(mbar), "r"(cnt) : "memory");
}
__device__ __forceinline__ void mbar_expect_tx(uint32_t mbar, uint32_t bytes) {
    asm volatile("mbarrier.arrive.expect_tx.shared.b64 _, [%0], %1;"
                 :: "r"(mbar), "r"(bytes) : "memory");
}
__device__ __forceinline__ void mbar_wait(uint32_t mbar, uint32_t parity) {
    asm volatile(
        "{\n\t.reg .pred P;\n"
        "WL%=:\n\t"
        "mbarrier.try_wait.parity.acquire.cta.shared::cta.b64 P, [%0], %1, 0x989680;\n\t"
        "@P bra WD%=;\n\t"
        "bra WL%=;\n"
        "WD%=:\n\t}"
        :: "r"(mbar), "r"(parity) : "memory");
}
__device__ __forceinline__ void bulk_g2s(uint32_t dst, const void* src,
                                         uint32_t bytes, uint32_t mbar) {
    asm volatile(
        "cp.async.bulk.shared::cta.global.mbarrier::complete_tx::bytes "
        "[%0], [%1], %2, [%3];"
        :: "r"(dst), "l"(src), "r"(bytes), "r"(mbar) : "memory");
}

// =============================================================================
// Generic SGEMM with bias: C[M,N] = A[M,K] @ B[K,N] + bias[N]
// 128x128 tile, BK=16, 256 threads, 8x8 per thread, f32x2 packed FMA.
// =============================================================================
__global__ void __launch_bounds__(256) sgemm_bias(
    const float* __restrict__ A, const float* __restrict__ B,
    const float* __restrict__ bias, float* __restrict__ C,
    int M, int N, int K)
{
    constexpr int BM = 128, BN = 128, BK = 16;
    __shared__ __align__(16) float As[BK][BM];
    __shared__ __align__(16) float Bs[BK][BN];

    const int tid  = threadIdx.x;
    const int bm   = blockIdx.y * BM;
    const int bn   = blockIdx.x * BN;
    const int trow = (tid >> 4) * 8;
    const int tcol = (tid & 15) * 8;

    uint64_t acc[4][8];
#pragma unroll
    for (int i = 0; i < 4; i++)
#pragma unroll
        for (int j = 0; j < 8; j++) acc[i][j] = 0ull;

    for (int k0 = 0; k0 < K; k0 += BK) {
#pragma unroll
        for (int l = 0; l < 2; l++) {
            int c   = tid * 2 + l;
            int row = c >> 2;
            int kq  = (c & 3) * 4;
            float4 v = *(const float4*)(A + (size_t)(bm + row) * K + k0 + kq);
            As[kq + 0][row] = v.x;
            As[kq + 1][row] = v.y;
            As[kq + 2][row] = v.z;
            As[kq + 3][row] = v.w;
        }
#pragma unroll
        for (int l = 0; l < 2; l++) {
            int c  = tid + (l << 8);
            int kr = c >> 5;
            int n4 = (c & 31) * 4;
            *(float4*)&Bs[kr][n4] =
                *(const float4*)(B + (size_t)(k0 + kr) * N + bn + n4);
        }
        __syncthreads();

#pragma unroll
        for (int kk = 0; kk < BK; kk++) {
            float4 a0 = *(const float4*)&As[kk][trow];
            float4 a1 = *(const float4*)&As[kk][trow + 4];
            float4 b0 = *(const float4*)&Bs[kk][tcol];
            float4 b1 = *(const float4*)&Bs[kk][tcol + 4];
            uint64_t ap[4];
            ap[0] = pack2(a0.x, a0.y);
            ap[1] = pack2(a0.z, a0.w);
            ap[2] = pack2(a1.x, a1.y);
            ap[3] = pack2(a1.z, a1.w);
            float bf[8] = {b0.x, b0.y, b0.z, b0.w, b1.x, b1.y, b1.z, b1.w};
#pragma unroll
            for (int j = 0; j < 8; j++) {
                uint64_t bd = pack2(bf[j], bf[j]);
#pragma unroll
                for (int i = 0; i < 4; i++) fma2(acc[i][j], ap[i], bd);
            }
        }
        __syncthreads();
    }

    float bv[8];
#pragma unroll
    for (int j = 0; j < 8; j++) bv[j] = bias[bn + tcol + j];

#pragma unroll
    for (int i = 0; i < 4; i++) {
        float o0[8], o1[8];
#pragma unroll
        for (int j = 0; j < 8; j++) {
            float2 v = unpack2(acc[i][j]);
            o0[j] = v.x + bv[j];
            o1[j] = v.y + bv[j];
        }
        size_t r0 = (size_t)(bm + trow + 2 * i) * N + bn + tcol;
        size_t r1 = r0 + N;
        *(float4*)(C + r0)     = make_float4(o0[0], o0[1], o0[2], o0[3]);
        *(float4*)(C + r0 + 4) = make_float4(o0[4], o0[5], o0[6], o0[7]);
        *(float4*)(C + r1)     = make_float4(o1[0], o1[1], o1[2], o1[3]);
        *(float4*)(C + r1 + 4) = make_float4(o1[4], o1[5], o1[6], o1[7]);
    }
}

// =============================================================================
// Persistent GRU scan v4 — cp.async.bulk h staging + SMEM compute.
//
// 128 CTAs x 512 threads, 1 CTA/SM (~181KB dyn SMEM). Per step:
//   - tid0 issues 2 cp.async.bulk chunks (rows 0-31 / 32-63 of padded h,
//     66048B each) global->SMEM with mbarrier complete_tx
//   - even warps (b 0..31) wait chunk0, odd warps chunk1  -> overlap
//   - per-thread dot: h slice via conflict-free LDS.128 (row stride 516),
//     W via warp-broadcast LDS.128, fma.rn.f32x2 accumulators
//   - k-segment reduce via padded SMEM, gating, stores (padded g_h + g_hs)
//   - grid barrier
// =============================================================================
#define NT   512
#define RPAD 97
#define HS_FLOATS  (BATCH * HROW)                 // 33024
#define WS_FLOATS  (2 * 256 * 12)                 // 6144
#define RED_FLOATS (BATCH * RPAD)                 // 6208
#define SCAN_SMEM  ((HS_FLOATS + WS_FLOATS + RED_FLOATS) * 4 + 16)  // 181520 B
#define CHUNK_BYTES (32 * HROW * 4)               // 66048

__global__ void __launch_bounds__(NT, 1) gru_scan(
    const float* __restrict__ Wh, const float* __restrict__ bhn)
{
    extern __shared__ float smem[];
    float*  h_sm = smem;                                  // [64][HROW]
    float2* wsm2 = (float2*)(smem + HS_FLOATS);           // [256 kp][12 c]
    float*  red  = smem + HS_FLOATS + WS_FLOATS;          // [64][RPAD]
    uint64_t* mbar = (uint64_t*)(smem + HS_FLOATS + WS_FLOATS + RED_FLOATS);

    const int tid = threadIdx.x;
    const int j0  = blockIdx.x * 4;

    const uint32_t h_sm_a = smem_u32(h_sm);
    const uint32_t mb0 = smem_u32(&mbar[0]);
    const uint32_t mb1 = smem_u32(&mbar[1]);

    if (tid == 0) { mbar_init(mb0, 1); mbar_init(mb1, 1); }

    // one-time W load, k-pair interleaved; c = jl*3 + g
    for (int i = tid; i < 256 * 12; i += NT) {
        int kp = i / 12, c = i % 12;
        int jl = c / 3, g = c - jl * 3;
        int col = g * HID + j0 + jl;
        float2 v;
        v.x = Wh[(size_t)(2 * kp)     * G3 + col];
        v.y = Wh[(size_t)(2 * kp + 1) * G3 + col];
        wsm2[i] = v;
    }
    __syncthreads();

    const int b    = tid & 63;        // compute role: batch
    const int kq   = tid >> 6;        // compute role: k-segment (0..7)
    const int mych = (tid >> 5) & 1;  // warp's h chunk (even warp: b<32)
    const uint32_t mymb = mych ? mb1 : mb0;
    const int rb   = tid >> 2;        // reducer role: batch  (tid < 256)
    const int rjl  = tid & 3;         // reducer role: local j
    const float bh = bhn[j0 + rjl];

    const ulonglong2* wp  = (const ulonglong2*)(wsm2 + (size_t)kq * 32 * 12);
    const ulonglong2* hme = (const ulonglong2*)(h_sm + b * HROW + kq * 64);

    const unsigned nblk = gridDim.x;

    for (int t = 0; t < T_STEPS; t++) {
        const float* hread  = g_h[t & 1];
        float*       hwrite = g_h[(t & 1) ^ 1];

        // ---- issue bulk h copy (single thread, both chunks) ----
        if (tid == 0) {
            mbar_expect_tx(mb0, CHUNK_BYTES);
            mbar_expect_tx(mb1, CHUNK_BYTES);
            bulk_g2s(h_sm_a, hread, CHUNK_BYTES, mb0);
            bulk_g2s(h_sm_a + CHUNK_BYTES,
                     (const char*)hread + CHUNK_BYTES, CHUNK_BYTES, mb1);
        }

        // ---- reducer xg prefetch (DRAM latency hides under copy/compute) ----
        float xr = 0.f, xz = 0.f, xn = 0.f;
        if (tid < 256) {
            size_t xb = ((size_t)t * BATCH + rb) * G3 + j0 + rjl;
            xr = __ldcg(&g_xg[xb]);
            xz = __ldcg(&g_xg[xb + HID]);
            xn = __ldcg(&g_xg[xb + 2 * HID]);
        }

        // ---- wait for my chunk, then 12 broadcast dot products ----
        mbar_wait(mymb, t & 1);

        uint64_t acc[12];
#pragma unroll
        for (int c = 0; c < 12; c++) acc[c] = 0ull;

#pragma unroll
        for (int i = 0; i < 16; i++) {
            ulonglong2 hh = hme[i];               // 2 k-pairs (4 floats)
#pragma unroll
            for (int m = 0; m < 6; m++) {
                ulonglong2 w = wp[(2 * i) * 6 + m];
                fma2(acc[2 * m],     hh.x, w.x);
                fma2(acc[2 * m + 1], hh.x, w.y);
            }
#pragma unroll
            for (int m = 0; m < 6; m++) {
                ulonglong2 w = wp[(2 * i + 1) * 6 + m];
                fma2(acc[2 * m],     hh.y, w.x);
                fma2(acc[2 * m + 1], hh.y, w.y);
            }
        }

        // ---- write partials (horizontal-add even/odd-k lanes) ----
#pragma unroll
        for (int c = 0; c < 12; c++) {
            float2 v = unpack2(acc[c]);
            red[b * RPAD + kq * 12 + c] = v.x + v.y;
        }
        __syncthreads();

        // ---- reduce 8 k-segments, gate, store ----
        if (tid < 256) {
            float hr = 0.f, hz = 0.f, hn = 0.f;
#pragma unroll
            for (int q = 0; q < 8; q++) {
                const float* rp = red + rb * RPAD + q * 12 + rjl * 3;
                hr += rp[0];
                hz += rp[1];
                hn += rp[2];
            }
            float r = 1.f / (1.f + __expf(-(xr + hr)));
            float z = 1.f / (1.f + __expf(-(xz + hz)));
            float n = tanhf(xn + r * (hn + bh));
            float hp = h_sm[rb * HROW + j0 + rjl];
            float hnew = (1.f - z) * n + z * hp;

            hwrite[rb * HROW + j0 + rjl] = hnew;
            g_hs[((size_t)t * BATCH + rb) * HID + j0 + rjl] = hnew;
        }

        // ---- grid barrier (release/acquire, monotonic counter) ----
        __syncthreads();
        if (tid == 0) {
            __threadfence();
            atomicAdd(&g_bar, 1u);
            unsigned target = nblk * (unsigned)(t + 1);
            while (*((volatile unsigned*)&g_bar) < target) { }
            __threadfence();
        }
        __syncthreads();
    }
}

// =============================================================================
extern "C" void kernel_launch(void* const* d_in, const int* in_sizes, int n_in,
                              void* d_out, int out_size)
{
    const float* x   = (const float*)d_in[0];
    const float* Wi  = (const float*)d_in[1];
    const float* bi  = (const float*)d_in[2];
    const float* Wh  = (const float*)d_in[3];
    const float* bhn = (const float*)d_in[4];
    const float* Wo  = (const float*)d_in[5];
    const float* bo  = (const float*)d_in[6];
    const float* h0  = (const float*)d_in[7];
    float* out = (float*)d_out;

    void *xg_p, *hs_p, *h_p, *bar_p;
    cudaGetSymbolAddress(&xg_p, g_xg);
    cudaGetSymbolAddress(&hs_p, g_hs);
    cudaGetSymbolAddress(&h_p,  g_h);
    cudaGetSymbolAddress(&bar_p, g_bar);

    cudaFuncSetAttribute(gru_scan, cudaFuncAttributeMaxDynamicSharedMemorySize,
                         SCAN_SMEM);

    cudaMemsetAsync(bar_p, 0, sizeof(unsigned), 0);
    // seed h0 into padded g_h[0] rows
    cudaMemcpy2DAsync(h_p, HROW * sizeof(float),
                      h0,  HID * sizeof(float),
                      HID * sizeof(float), BATCH,
                      cudaMemcpyDeviceToDevice, 0);

    // 1) xg = x @ Wi + bi   : [65536,256]x[256,1536]
    {
        dim3 grid(G3 / 128, (T_STEPS * BATCH) / 128);
        sgemm_bias<<<grid, 256>>>(x, Wi, bi, (float*)xg_p,
                                  T_STEPS * BATCH, G3, DIN);
    }

    // 2) persistent GRU scan over T=1024 steps
    gru_scan<<<HID / 4, NT, SCAN_SMEM>>>(Wh, bhn);

    // 3) out = hs @ Wo + bo : [65536,512]x[512,256]
    {
        dim3 grid(OUTD / 128, (T_STEPS * BATCH) / 128);
        sgemm_bias<<<grid, 256>>>((const float*)hs_p, Wo, bo, out,
                                  T_STEPS * BATCH, OUTD, HID);
    }
}

// round 11
// speedup vs baseline: 2.5059x; 1.0037x over previous
#include <cuda_runtime.h>
#include <cstdint>

#define T_STEPS 1024
#define BATCH   64
#define DIN     256
#define HID     512
#define OUTD    256
#define G3      1536   // 3*HID
#define HROW    516    // padded h row stride (floats)

// ---------------- persistent scratch (device globals; no allocation) ----------
__device__ float g_xg[(size_t)T_STEPS * BATCH * G3];   // ~402 MB
__device__ float g_hs[(size_t)T_STEPS * BATCH * HID];  // ~134 MB
__device__ __align__(256) float g_h[2][BATCH * HROW];  // padded, bulk-copyable
__device__ unsigned int g_bar;

// ---------------- packed f32x2 + async helpers --------------------------------
__device__ __forceinline__ void fma2(uint64_t& d, uint64_t a, uint64_t b) {
    asm("fma.rn.f32x2 %0, %1, %2, %0;" : "+l"(d) : "l"(a), "l"(b));
}
__device__ __forceinline__ uint64_t pack2(float lo, float hi) {
    uint64_t r;
    asm("mov.b64 %0, {%1, %2};" : "=l"(r) : "f"(lo), "f"(hi));
    return r;
}
__device__ __forceinline__ float2 unpack2(uint64_t v) {
    float2 f;
    asm("mov.b64 {%0, %1}, %2;" : "=f"(f.x), "=f"(f.y) : "l"(v));
    return f;
}
__device__ __forceinline__ uint32_t smem_u32(const void* p) {
    uint32_t a;
    asm("{ .reg .u64 t; cvta.to.shared.u64 t, %1; cvt.u32.u64 %0, t; }"
        : "=r"(a) : "l"(p));
    return a;
}
__device__ __forceinline__ void mbar_init(uint32_t mbar, uint32_t cnt) {
    asm volatile("mbarrier.init.shared.b64 [%0], %1;" :: "r"(mbar), "r"(cnt) : "memory");
}
__device__ __forceinline__ void mbar_expect_tx(uint32_t mbar, uint32_t bytes) {
    asm volatile("mbarrier.arrive.expect_tx.shared.b64 _, [%0], %1;"
                 :: "r"(mbar), "r"(bytes) : "memory");
}
__device__ __forceinline__ void mbar_wait(uint32_t mbar, uint32_t parity) {
    asm volatile(
        "{\n\t.reg .pred P;\n"
        "WL%=:\n\t"
        "mbarrier.try_wait.parity.acquire.cta.shared::cta.b64 P, [%0], %1, 0x989680;\n\t"
        "@P bra WD%=;\n\t"
        "bra WL%=;\n"
        "WD%=:\n\t}"
        :: "r"(mbar), "r"(parity) : "memory");
}
// multicast bulk copy: delivers data + complete_tx to every cluster CTA in mask
__device__ __forceinline__ void bulk_g2s_mc(uint32_t dst, const void* src,
                                            uint32_t bytes, uint32_t mbar,
                                            uint16_t mask) {
    asm volatile(
        "cp.async.bulk.shared::cluster.global.mbarrier::complete_tx::bytes"
        ".multicast::cluster [%0], [%1], %2, [%3], %4;"
        :: "r"(dst), "l"(src), "r"(bytes), "r"(mbar), "h"(mask) : "memory");
}

// =============================================================================
// SGEMM with bias: C[M,N] = A[M,K] @ B[K,N] + bias[N]
// 128x128 tile, BK=16, 256 threads. Warp footprint 32 rows x 64 cols; thread
// tile = 8 rows x (4+4 split cols) -> all smem reads phase-dense LDS.128.
// Accumulators packed over column pairs (b is the packed fma2 operand).
// =============================================================================
__global__ void __launch_bounds__(256) sgemm_bias(
    const float* __restrict__ A, const float* __restrict__ B,
    const float* __restrict__ bias, float* __restrict__ C,
    int M, int N, int K)
{
    constexpr int BM = 128, BN = 128, BK = 16;
    __shared__ __align__(16) float As[BK][BM];
    __shared__ __align__(16) float Bs[BK][BN];

    const int tid  = threadIdx.x;
    const int w    = tid >> 5;
    const int lane = tid & 31;
    const int r    = (lane >> 3) + ((w >> 1) << 2);   // 0..15
    const int c    = (lane & 7) + ((w & 1) << 3);     // 0..15
    const int trow = r * 8;
    const int tc1  = c * 4;
    const int tc2  = c * 4 + 64;
    const int bm   = blockIdx.y * BM;
    const int bn   = blockIdx.x * BN;

    uint64_t acc[8][4];
#pragma unroll
    for (int i = 0; i < 8; i++)
#pragma unroll
        for (int j = 0; j < 4; j++) acc[i][j] = 0ull;

    for (int k0 = 0; k0 < K; k0 += BK) {
#pragma unroll
        for (int l = 0; l < 2; l++) {
            int cc  = tid * 2 + l;
            int row = cc >> 2;
            int kq  = (cc & 3) * 4;
            float4 v = *(const float4*)(A + (size_t)(bm + row) * K + k0 + kq);
            As[kq + 0][row] = v.x;
            As[kq + 1][row] = v.y;
            As[kq + 2][row] = v.z;
            As[kq + 3][row] = v.w;
        }
#pragma unroll
        for (int l = 0; l < 2; l++) {
            int cc = tid + (l << 8);
            int kr = cc >> 5;
            int n4 = (cc & 31) * 4;
            *(float4*)&Bs[kr][n4] =
                *(const float4*)(B + (size_t)(k0 + kr) * N + bn + n4);
        }
        __syncthreads();

#pragma unroll
        for (int kk = 0; kk < BK; kk++) {
            float4 a0 = *(const float4*)&As[kk][trow];
            float4 a1 = *(const float4*)&As[kk][trow + 4];
            ulonglong2 b01 = *(const ulonglong2*)&Bs[kk][tc1];
            ulonglong2 b23 = *(const ulonglong2*)&Bs[kk][tc2];
            float af[8] = {a0.x, a0.y, a0.z, a0.w, a1.x, a1.y, a1.z, a1.w};
#pragma unroll
            for (int i = 0; i < 8; i++) {
                uint64_t ad = pack2(af[i], af[i]);
                fma2(acc[i][0], ad, b01.x);
                fma2(acc[i][1], ad, b01.y);
                fma2(acc[i][2], ad, b23.x);
                fma2(acc[i][3], ad, b23.y);
            }
        }
        __syncthreads();
    }

    float bv1[4], bv2[4];
#pragma unroll
    for (int j = 0; j < 4; j++) {
        bv1[j] = bias[bn + tc1 + j];
        bv2[j] = bias[bn + tc2 + j];
    }

#pragma unroll
    for (int i = 0; i < 8; i++) {
        float2 p0 = unpack2(acc[i][0]);
        float2 p1 = unpack2(acc[i][1]);
        float2 p2 = unpack2(acc[i][2]);
        float2 p3 = unpack2(acc[i][3]);
        size_t row = (size_t)(bm + trow + i) * N + bn;
        *(float4*)(C + row + tc1) = make_float4(p0.x + bv1[0], p0.y + bv1[1],
                                                p1.x + bv1[2], p1.y + bv1[3]);
        *(float4*)(C + row + tc2) = make_float4(p2.x + bv2[0], p2.y + bv2[1],
                                                p3.x + bv2[2], p3.y + bv2[3]);
    }
}

// =============================================================================
// Persistent GRU scan v5 — cluster(4) multicast h staging.
//
// 128 CTAs (32 clusters of 4) x 512 threads, 1 CTA/SM. Per step:
//   - tid0: expect_tx on both chunk mbarriers, THEN global barrier, THEN issue
//     its rank's h slice (33KB) as a multicast bulk copy to all 4 cluster CTAs.
//     Ordering: expect_tx < barrier-arrive < barrier-release < any issue, so
//     tx-arrivals can never precede expect_tx, and no CTA's h_sm is overwritten
//     while still being read (reads finish before that CTA's barrier arrive).
//   - compute warps wait their chunk's mbar (rows 0-31 / 32-63), dot products
//     from SMEM (broadcast-W LDS.128 + fma.rn.f32x2), k-reduce, gate, store.
// L2 read traffic per step drops 16.9MB -> ~4.2MB (multicast dedup).
// =============================================================================
#define NT   512
#define RPAD 97
#define HS_FLOATS  (BATCH * HROW)                 // 33024
#define WS_FLOATS  (2 * 256 * 12)                 // 6144
#define RED_FLOATS (BATCH * RPAD)                 // 6208
#define SCAN_SMEM  ((HS_FLOATS + WS_FLOATS + RED_FLOATS) * 4 + 16)  // 181520 B
#define SLICE_BYTES  (16 * HROW * 4)              // 33024 (16 batch rows)
#define CHUNK_BYTES  (2 * SLICE_BYTES)            // 66048 (32 batch rows)

__global__ void __launch_bounds__(NT, 1) __cluster_dims__(4, 1, 1)
gru_scan(const float* __restrict__ Wh, const float* __restrict__ bhn)
{
    extern __shared__ float smem[];
    float*  h_sm = smem;                                  // [64][HROW]
    float2* wsm2 = (float2*)(smem + HS_FLOATS);           // [256 kp][12 c]
    float*  red  = smem + HS_FLOATS + WS_FLOATS;          // [64][RPAD]
    uint64_t* mbar = (uint64_t*)(smem + HS_FLOATS + WS_FLOATS + RED_FLOATS);

    const int tid = threadIdx.x;
    const int j0  = blockIdx.x * 4;

    uint32_t rank;
    asm("mov.u32 %0, %%cluster_ctarank;" : "=r"(rank));

    const uint32_t h_sm_a = smem_u32(h_sm);
    const uint32_t mb0 = smem_u32(&mbar[0]);
    const uint32_t mb1 = smem_u32(&mbar[1]);
    const uint32_t mymbar_for_slice = (rank < 2) ? mb0 : mb1;

    if (tid == 0) { mbar_init(mb0, 1); mbar_init(mb1, 1); }

    // one-time W load, k-pair interleaved; c = jl*3 + g
    for (int i = tid; i < 256 * 12; i += NT) {
        int kp = i / 12, cc = i % 12;
        int jl = cc / 3, g = cc - jl * 3;
        int col = g * HID + j0 + jl;
        float2 v;
        v.x = Wh[(size_t)(2 * kp)     * G3 + col];
        v.y = Wh[(size_t)(2 * kp + 1) * G3 + col];
        wsm2[i] = v;
    }
    __syncthreads();
    // all cluster CTAs' mbarriers inited before any multicast can target them
    asm volatile("barrier.cluster.arrive.aligned;" ::: "memory");
    asm volatile("barrier.cluster.wait.aligned;" ::: "memory");

    const int b    = tid & 63;        // compute role: batch
    const int kq   = tid >> 6;        // compute role: k-segment (0..7)
    const int mych = (tid >> 5) & 1;  // warp's h chunk (b<32 ? 0 : 1)
    const uint32_t mymb = mych ? mb1 : mb0;
    const int rb   = tid >> 2;        // reducer role: batch  (tid < 256)
    const int rjl  = tid & 3;         // reducer role: local j
    const float bh = bhn[j0 + rjl];

    const ulonglong2* wp  = (const ulonglong2*)(wsm2 + (size_t)kq * 32 * 12);
    const ulonglong2* hme = (const ulonglong2*)(h_sm + b * HROW + kq * 64);

    const unsigned nblk = gridDim.x;

    for (int t = 0; t < T_STEPS; t++) {
        const float* hread  = g_h[t & 1];
        float*       hwrite = g_h[(t & 1) ^ 1];

        if (tid == 0) {
            // expect BEFORE barrier arrive: no tx can land earlier
            mbar_expect_tx(mb0, CHUNK_BYTES);
            mbar_expect_tx(mb1, CHUNK_BYTES);
            // global barrier (release/acquire, monotonic counter)
            __threadfence();
            atomicAdd(&g_bar, 1u);
            unsigned target = nblk * (unsigned)(t + 1);
            while (*((volatile unsigned*)&g_bar) < target) { }
            __threadfence();
            // issue my rank's slice, multicast to whole cluster
            bulk_g2s_mc(h_sm_a + rank * SLICE_BYTES,
                        (const char*)hread + rank * SLICE_BYTES,
                        SLICE_BYTES, mymbar_for_slice, (uint16_t)0xF);
        }

        // ---- reducer xg prefetch (DRAM latency hides under copy wait) ----
        float xr = 0.f, xz = 0.f, xn = 0.f;
        if (tid < 256) {
            size_t xb = ((size_t)t * BATCH + rb) * G3 + j0 + rjl;
            xr = __ldcg(&g_xg[xb]);
            xz = __ldcg(&g_xg[xb + HID]);
            xn = __ldcg(&g_xg[xb + 2 * HID]);
        }

        // ---- wait for my chunk, then 12 broadcast dot products ----
        mbar_wait(mymb, t & 1);

        uint64_t acc[12];
#pragma unroll
        for (int cc = 0; cc < 12; cc++) acc[cc] = 0ull;

#pragma unroll
        for (int i = 0; i < 16; i++) {
            ulonglong2 hh = hme[i];               // 2 k-pairs (4 floats)
#pragma unroll
            for (int m = 0; m < 6; m++) {
                ulonglong2 wv = wp[(2 * i) * 6 + m];
                fma2(acc[2 * m],     hh.x, wv.x);
                fma2(acc[2 * m + 1], hh.x, wv.y);
            }
#pragma unroll
            for (int m = 0; m < 6; m++) {
                ulonglong2 wv = wp[(2 * i + 1) * 6 + m];
                fma2(acc[2 * m],     hh.y, wv.x);
                fma2(acc[2 * m + 1], hh.y, wv.y);
            }
        }

#pragma unroll
        for (int cc = 0; cc < 12; cc++) {
            float2 v = unpack2(acc[cc]);
            red[b * RPAD + kq * 12 + cc] = v.x + v.y;
        }
        __syncthreads();

        // ---- reduce 8 k-segments, gate, store ----
        if (tid < 256) {
            float hr = 0.f, hz = 0.f, hn = 0.f;
#pragma unroll
            for (int q = 0; q < 8; q++) {
                const float* rp = red + rb * RPAD + q * 12 + rjl * 3;
                hr += rp[0];
                hz += rp[1];
                hn += rp[2];
            }
            float rg = 1.f / (1.f + __expf(-(xr + hr)));
            float zg = 1.f / (1.f + __expf(-(xz + hz)));
            float ng = tanhf(xn + rg * (hn + bh));
            float hp = h_sm[rb * HROW + j0 + rjl];
            float hnew = (1.f - zg) * ng + zg * hp;

            hwrite[rb * HROW + j0 + rjl] = hnew;
            g_hs[((size_t)t * BATCH + rb) * HID + j0 + rjl] = hnew;
        }
        __syncthreads();   // all stores done before next-iter barrier arrive
    }

    asm volatile("barrier.cluster.arrive.aligned;" ::: "memory");
    asm volatile("barrier.cluster.wait.aligned;" ::: "memory");
}

// no-op tail kernel: shifts ncu's -s5-c1 window onto gru_scan (launch #6)
__global__ void tail_noop() {}

// =============================================================================
extern "C" void kernel_launch(void* const* d_in, const int* in_sizes, int n_in,
                              void* d_out, int out_size)
{
    const float* x   = (const float*)d_in[0];
    const float* Wi  = (const float*)d_in[1];
    const float* bi  = (const float*)d_in[2];
    const float* Wh  = (const float*)d_in[3];
    const float* bhn = (const float*)d_in[4];
    const float* Wo  = (const float*)d_in[5];
    const float* bo  = (const float*)d_in[6];
    const float* h0  = (const float*)d_in[7];
    float* out = (float*)d_out;

    void *xg_p, *hs_p, *h_p, *bar_p;
    cudaGetSymbolAddress(&xg_p, g_xg);
    cudaGetSymbolAddress(&hs_p, g_hs);
    cudaGetSymbolAddress(&h_p,  g_h);
    cudaGetSymbolAddress(&bar_p, g_bar);

    cudaFuncSetAttribute(gru_scan, cudaFuncAttributeMaxDynamicSharedMemorySize,
                         SCAN_SMEM);

    cudaMemsetAsync(bar_p, 0, sizeof(unsigned), 0);
    // seed h0 into padded g_h[0] rows
    cudaMemcpy2DAsync(h_p, HROW * sizeof(float),
                      h0,  HID * sizeof(float),
                      HID * sizeof(float), BATCH,
                      cudaMemcpyDeviceToDevice, 0);

    // 1) xg = x @ Wi + bi   : [65536,256]x[256,1536]
    {
        dim3 grid(G3 / 128, (T_STEPS * BATCH) / 128);
        sgemm_bias<<<grid, 256>>>(x, Wi, bi, (float*)xg_p,
                                  T_STEPS * BATCH, G3, DIN);
    }

    // 2) persistent GRU scan over T=1024 steps (32 clusters of 4)
    gru_scan<<<HID / 4, NT, SCAN_SMEM>>>(Wh, bhn);

    // 3) out = hs @ Wo + bo : [65536,512]x[512,256]
    {
        dim3 grid(OUTD / 128, (T_STEPS * BATCH) / 128);
        sgemm_bias<<<grid, 256>>>((const float*)hs_p, Wo, bo, out,
                                  T_STEPS * BATCH, OUTD, HID);
    }

    // 4) profiling phase-shift
    tail_noop<<<1, 32>>>();
}

// round 13
// speedup vs baseline: 2.8126x; 1.1224x over previous
#include <cuda_runtime.h>
#include <cstdint>

#define T_STEPS 1024
#define BATCH   64
#define DIN     256
#define HID     512
#define OUTD    256
#define G3      1536   // 3*HID
#define HROW    516    // padded h row stride (floats)

// ---------------- persistent scratch (device globals; no allocation) ----------
__device__ float g_xg[(size_t)T_STEPS * BATCH * G3];   // ~402 MB
__device__ float g_hs[(size_t)T_STEPS * BATCH * HID];  // ~134 MB
__device__ __align__(256) float g_h[2][BATCH * HROW];  // padded, bulk-copyable
__device__ unsigned int g_bar;

// ---------------- packed f32x2 + async helpers --------------------------------
__device__ __forceinline__ void fma2(uint64_t& d, uint64_t a, uint64_t b) {
    asm("fma.rn.f32x2 %0, %1, %2, %0;" : "+l"(d) : "l"(a), "l"(b));
}
__device__ __forceinline__ uint64_t pack2(float lo, float hi) {
    uint64_t r;
    asm("mov.b64 %0, {%1, %2};" : "=l"(r) : "f"(lo), "f"(hi));
    return r;
}
__device__ __forceinline__ float2 unpack2(uint64_t v) {
    float2 f;
    asm("mov.b64 {%0, %1}, %2;" : "=f"(f.x), "=f"(f.y) : "l"(v));
    return f;
}
__device__ __forceinline__ uint32_t smem_u32(const void* p) {
    uint32_t a;
    asm("{ .reg .u64 t; cvta.to.shared.u64 t, %1; cvt.u32.u64 %0, t; }"
        : "=r"(a) : "l"(p));
    return a;
}
__device__ __forceinline__ void mbar_init(uint32_t mbar, uint32_t cnt) {
    asm volatile("mbarrier.init.shared.b64 [%0], %1;" :: "r"(mbar), "r"(cnt) : "memory");
}
__device__ __forceinline__ void mbar_expect_tx(uint32_t mbar, uint32_t bytes) {
    asm volatile("mbarrier.arrive.expect_tx.shared.b64 _, [%0], %1;"
                 :: "r"(mbar), "r"(bytes) : "memory");
}
__device__ __forceinline__ void mbar_wait(uint32_t mbar, uint32_t parity) {
    asm volatile(
        "{\n\t.reg .pred P;\n"
        "WL%=:\n\t"
        "mbarrier.try_wait.parity.acquire.cta.shared::cta.b64 P, [%0], %1, 0x989680;\n\t"
        "@P bra WD%=;\n\t"
        "bra WL%=;\n"
        "WD%=:\n\t}"
        :: "r"(mbar), "r"(parity) : "memory");
}
__device__ __forceinline__ void bulk_g2s_mc(uint32_t dst, const void* src,
                                            uint32_t bytes, uint32_t mbar,
                                            uint16_t mask) {
    asm volatile(
        "cp.async.bulk.shared::cluster.global.mbarrier::complete_tx::bytes"
        ".multicast::cluster [%0], [%1], %2, [%3], %4;"
        :: "r"(dst), "l"(src), "r"(bytes), "r"(mbar), "h"(mask) : "memory");
}

// =============================================================================
// SGEMM with bias: C[M,N] = A[M,K] @ B[K,N] + bias[N]  (unchanged this round)
// =============================================================================
__global__ void __launch_bounds__(256) sgemm_bias(
    const float* __restrict__ A, const float* __restrict__ B,
    const float* __restrict__ bias, float* __restrict__ C,
    int M, int N, int K)
{
    constexpr int BM = 128, BN = 128, BK = 16;
    __shared__ __align__(16) float As[BK][BM];
    __shared__ __align__(16) float Bs[BK][BN];

    const int tid  = threadIdx.x;
    const int w    = tid >> 5;
    const int lane = tid & 31;
    const int r    = (lane >> 3) + ((w >> 1) << 2);
    const int c    = (lane & 7) + ((w & 1) << 3);
    const int trow = r * 8;
    const int tc1  = c * 4;
    const int tc2  = c * 4 + 64;
    const int bm   = blockIdx.y * BM;
    const int bn   = blockIdx.x * BN;

    uint64_t acc[8][4];
#pragma unroll
    for (int i = 0; i < 8; i++)
#pragma unroll
        for (int j = 0; j < 4; j++) acc[i][j] = 0ull;

    for (int k0 = 0; k0 < K; k0 += BK) {
#pragma unroll
        for (int l = 0; l < 2; l++) {
            int cc  = tid * 2 + l;
            int row = cc >> 2;
            int kq  = (cc & 3) * 4;
            float4 v = *(const float4*)(A + (size_t)(bm + row) * K + k0 + kq);
            As[kq + 0][row] = v.x;
            As[kq + 1][row] = v.y;
            As[kq + 2][row] = v.z;
            As[kq + 3][row] = v.w;
        }
#pragma unroll
        for (int l = 0; l < 2; l++) {
            int cc = tid + (l << 8);
            int kr = cc >> 5;
            int n4 = (cc & 31) * 4;
            *(float4*)&Bs[kr][n4] =
                *(const float4*)(B + (size_t)(k0 + kr) * N + bn + n4);
        }
        __syncthreads();

#pragma unroll
        for (int kk = 0; kk < BK; kk++) {
            float4 a0 = *(const float4*)&As[kk][trow];
            float4 a1 = *(const float4*)&As[kk][trow + 4];
            ulonglong2 b01 = *(const ulonglong2*)&Bs[kk][tc1];
            ulonglong2 b23 = *(const ulonglong2*)&Bs[kk][tc2];
            float af[8] = {a0.x, a0.y, a0.z, a0.w, a1.x, a1.y, a1.z, a1.w};
#pragma unroll
            for (int i = 0; i < 8; i++) {
                uint64_t ad = pack2(af[i], af[i]);
                fma2(acc[i][0], ad, b01.x);
                fma2(acc[i][1], ad, b01.y);
                fma2(acc[i][2], ad, b23.x);
                fma2(acc[i][3], ad, b23.y);
            }
        }
        __syncthreads();
    }

    float bv1[4], bv2[4];
#pragma unroll
    for (int j = 0; j < 4; j++) {
        bv1[j] = bias[bn + tc1 + j];
        bv2[j] = bias[bn + tc2 + j];
    }

#pragma unroll
    for (int i = 0; i < 8; i++) {
        float2 p0 = unpack2(acc[i][0]);
        float2 p1 = unpack2(acc[i][1]);
        float2 p2 = unpack2(acc[i][2]);
        float2 p3 = unpack2(acc[i][3]);
        size_t row = (size_t)(bm + trow + i) * N + bn;
        *(float4*)(C + row + tc1) = make_float4(p0.x + bv1[0], p0.y + bv1[1],
                                                p1.x + bv1[2], p1.y + bv1[3]);
        *(float4*)(C + row + tc2) = make_float4(p2.x + bv2[0], p2.y + bv2[1],
                                                p3.x + bv2[2], p3.y + bv2[3]);
    }
}

// =============================================================================
// Persistent GRU scan v6 — 2-batches-per-thread, halved W traffic.
//
// 128 CTAs (32 clusters of 4) x 512 threads, 1 CTA/SM. Thread = (lane bb:
// batches bb & bb+32, warp kq: k-segment of 32). Each broadcast W load now
// feeds TWO batches -> per-warp LDS phases 256 -> 160, FMA becomes binder.
// Per step: expect_tx -> global barrier -> cluster-multicast h slices (4 x
// 33KB) -> single mbar wait -> 24 packed dots -> 16-seg reduce -> gate/store.
// =============================================================================
#define NT    512
#define RPAD2 193                                 // 16*12 + 1
#define HS_FLOATS  (BATCH * HROW)                 // 33024
#define WS_FLOATS  (2 * 256 * 12)                 // 6144
#define RED_FLOATS (BATCH * RPAD2)                // 12352
#define SCAN_SMEM  ((HS_FLOATS + WS_FLOATS + RED_FLOATS) * 4 + 16)  // 206096 B
#define SLICE_BYTES (16 * HROW * 4)               // 33024
#define H_BYTES     (4 * SLICE_BYTES)             // 132096

__global__ void __launch_bounds__(NT, 1) __cluster_dims__(4, 1, 1)
gru_scan(const float* __restrict__ Wh, const float* __restrict__ bhn)
{
    extern __shared__ float smem[];
    float*  h_sm = smem;                                  // [64][HROW]
    float2* wsm2 = (float2*)(smem + HS_FLOATS);           // [256 kp][12 c]
    float*  red  = smem + HS_FLOATS + WS_FLOATS;          // [64][RPAD2]
    uint64_t* mbar = (uint64_t*)(smem + HS_FLOATS + WS_FLOATS + RED_FLOATS);

    const int tid = threadIdx.x;
    const int j0  = blockIdx.x * 4;

    uint32_t rank;
    asm("mov.u32 %0, %%cluster_ctarank;" : "=r"(rank));

    const uint32_t h_sm_a = smem_u32(h_sm);
    const uint32_t mb0 = smem_u32(&mbar[0]);

    if (tid == 0) mbar_init(mb0, 1);

    // one-time W load, k-pair interleaved; wsm2[kp*12+c] = (W[2kp,c],W[2kp+1,c])
    for (int i = tid; i < 256 * 12; i += NT) {
        int kp = i / 12, cc = i % 12;
        int jl = cc / 3, g = cc - jl * 3;
        int col = g * HID + j0 + jl;
        float2 v;
        v.x = Wh[(size_t)(2 * kp)     * G3 + col];
        v.y = Wh[(size_t)(2 * kp + 1) * G3 + col];
        wsm2[i] = v;
    }
    __syncthreads();
    asm volatile("barrier.cluster.arrive.aligned;" ::: "memory");
    asm volatile("barrier.cluster.wait.aligned;" ::: "memory");

    const int bb  = tid & 31;         // compute role: batch pair (bb, bb+32)
    const int kq  = tid >> 5;         // compute role: k-segment (0..15), warp-uniform
    const int rb  = tid >> 2;         // reducer role: batch (tid < 256)
    const int rjl = tid & 3;          // reducer role: local j
    const float bh = bhn[j0 + rjl];

    const ulonglong2* hmeA = (const ulonglong2*)(h_sm + bb * HROW + kq * 32);
    const ulonglong2* hmeB = (const ulonglong2*)(h_sm + (bb + 32) * HROW + kq * 32);
    const float2* wbase = wsm2 + (size_t)kq * 16 * 12;

    const unsigned nblk = gridDim.x;

    for (int t = 0; t < T_STEPS; t++) {
        const float* hread  = g_h[t & 1];
        float*       hwrite = g_h[(t & 1) ^ 1];

        if (tid == 0) {
            mbar_expect_tx(mb0, H_BYTES);      // before barrier arrive
            __threadfence();
            atomicAdd(&g_bar, 1u);
            unsigned target = nblk * (unsigned)(t + 1);
            while (*((volatile unsigned*)&g_bar) < target) { }
            __threadfence();
            bulk_g2s_mc(h_sm_a + rank * SLICE_BYTES,
                        (const char*)hread + rank * SLICE_BYTES,
                        SLICE_BYTES, mb0, (uint16_t)0xF);
        }

        // reducer xg prefetch (DRAM latency hides under barrier/copy)
        float xr = 0.f, xz = 0.f, xn = 0.f;
        if (tid < 256) {
            size_t xb = ((size_t)t * BATCH + rb) * G3 + j0 + rjl;
            xr = __ldcg(&g_xg[xb]);
            xz = __ldcg(&g_xg[xb + HID]);
            xn = __ldcg(&g_xg[xb + 2 * HID]);
        }

        mbar_wait(mb0, t & 1);

        uint64_t accA[12], accB[12];
#pragma unroll
        for (int cc = 0; cc < 12; cc++) { accA[cc] = 0ull; accB[cc] = 0ull; }

#pragma unroll
        for (int i = 0; i < 8; i++) {            // 2 k-pairs per i
            ulonglong2 hA = hmeA[i];
            ulonglong2 hB = hmeB[i];
            const ulonglong2* w0 = (const ulonglong2*)(wbase + (2 * i) * 12);
#pragma unroll
            for (int m = 0; m < 6; m++) {        // kp = kq*16 + 2i
                ulonglong2 wv = w0[m];
                fma2(accA[2 * m],     hA.x, wv.x);
                fma2(accA[2 * m + 1], hA.x, wv.y);
                fma2(accB[2 * m],     hB.x, wv.x);
                fma2(accB[2 * m + 1], hB.x, wv.y);
            }
#pragma unroll
            for (int m = 0; m < 6; m++) {        // kp = kq*16 + 2i + 1
                ulonglong2 wv = w0[6 + m];
                fma2(accA[2 * m],     hA.y, wv.x);
                fma2(accA[2 * m + 1], hA.y, wv.y);
                fma2(accB[2 * m],     hB.y, wv.x);
                fma2(accB[2 * m + 1], hB.y, wv.y);
            }
        }

        // partials: red[b][kq*12+c]   (stride-193 rows: conflict-free STS)
#pragma unroll
        for (int cc = 0; cc < 12; cc++) {
            float2 v = unpack2(accA[cc]);
            red[bb * RPAD2 + kq * 12 + cc] = v.x + v.y;
        }
#pragma unroll
        for (int cc = 0; cc < 12; cc++) {
            float2 v = unpack2(accB[cc]);
            red[(bb + 32) * RPAD2 + kq * 12 + cc] = v.x + v.y;
        }
        __syncthreads();

        // reduce 16 k-segments, gate, store
        if (tid < 256) {
            float hr = 0.f, hz = 0.f, hn = 0.f;
#pragma unroll
            for (int q = 0; q < 16; q++) {
                const float* rp = red + rb * RPAD2 + q * 12 + rjl * 3;
                hr += rp[0];
                hz += rp[1];
                hn += rp[2];
            }
            float rg = 1.f / (1.f + __expf(-(xr + hr)));
            float zg = 1.f / (1.f + __expf(-(xz + hz)));
            float ng = tanhf(xn + rg * (hn + bh));
            float hp = h_sm[rb * HROW + j0 + rjl];
            float hnew = (1.f - zg) * ng + zg * hp;

            hwrite[rb * HROW + j0 + rjl] = hnew;
            g_hs[((size_t)t * BATCH + rb) * HID + j0 + rjl] = hnew;
        }
        __syncthreads();   // all reads/stores done before next-iter arrive
    }

    asm volatile("barrier.cluster.arrive.aligned;" ::: "memory");
    asm volatile("barrier.cluster.wait.aligned;" ::: "memory");
}

// no-op: shifts ncu's -s5-c1 window so launch #6 == gru_scan
__global__ void pad_noop() {}

// =============================================================================
extern "C" void kernel_launch(void* const* d_in, const int* in_sizes, int n_in,
                              void* d_out, int out_size)
{
    const float* x   = (const float*)d_in[0];
    const float* Wi  = (const float*)d_in[1];
    const float* bi  = (const float*)d_in[2];
    const float* Wh  = (const float*)d_in[3];
    const float* bhn = (const float*)d_in[4];
    const float* Wo  = (const float*)d_in[5];
    const float* bo  = (const float*)d_in[6];
    const float* h0  = (const float*)d_in[7];
    float* out = (float*)d_out;

    void *xg_p, *hs_p, *h_p, *bar_p;
    cudaGetSymbolAddress(&xg_p, g_xg);
    cudaGetSymbolAddress(&hs_p, g_hs);
    cudaGetSymbolAddress(&h_p,  g_h);
    cudaGetSymbolAddress(&bar_p, g_bar);

    cudaFuncSetAttribute(gru_scan, cudaFuncAttributeMaxDynamicSharedMemorySize,
                         SCAN_SMEM);

    cudaMemsetAsync(bar_p, 0, sizeof(unsigned), 0);                      // launch 1
    cudaMemcpy2DAsync(h_p, HROW * sizeof(float),
                      h0,  HID * sizeof(float),
                      HID * sizeof(float), BATCH,
                      cudaMemcpyDeviceToDevice, 0);                      // launch 2

    // 1) xg = x @ Wi + bi
    {
        dim3 grid(G3 / 128, (T_STEPS * BATCH) / 128);
        sgemm_bias<<<grid, 256>>>(x, Wi, bi, (float*)xg_p,
                                  T_STEPS * BATCH, G3, DIN);             // launch 3
    }

    pad_noop<<<1, 32>>>();                                               // launch 4
    pad_noop<<<1, 32>>>();                                               // launch 5

    // 2) persistent GRU scan (32 clusters of 4)
    gru_scan<<<HID / 4, NT, SCAN_SMEM>>>(Wh, bhn);                       // launch 6

    // 3) out = hs @ Wo + bo
    {
        dim3 grid(OUTD / 128, (T_STEPS * BATCH) / 128);
        sgemm_bias<<<grid, 256>>>((const float*)hs_p, Wo, bo, out,
                                  T_STEPS * BATCH, OUTD, HID);
    }
}